// round 15
// baseline (speedup 1.0000x reference)
#include <cuda_runtime.h>
#include <cuda_bf16.h>
#include <math.h>
#include <stdint.h>

// Problem constants
#define NN   10000
#define EE   160000
#define ET   170000          // EE + NN self loops
#define DIN  512
#define HID  1024
#define NEG  0.2f
#define DCAP 512             // cached edges per dst (layers 1-2)
#define DCAP3 256            // cached edges per dst (layer 3)

// ---------------------------------------------------------------------------
// Scratch (device globals; no allocation allowed)
// ---------------------------------------------------------------------------
__device__ __align__(256) float g_h   [(size_t)NN * HID];
__device__ __align__(256) float g_lin [(size_t)NN * HID];
__device__ __align__(256) float g_als [NN * 6];
__device__ __align__(256) float g_ald [NN * 6];
__device__ __align__(256) float g_h3  [NN * 36];
__device__ __align__(256) float g_lin3[NN * 6];
__device__ __align__(256) __nv_bfloat16 g_Axh[(size_t)NN * HID];
__device__ __align__(256) __nv_bfloat16 g_Axl[(size_t)NN * HID];
__device__ __align__(256) __nv_bfloat16 g_Bth[(size_t)2048 * 1024];
__device__ __align__(256) __nv_bfloat16 g_Btl[(size_t)2048 * 1024];
__device__ __align__(256) __nv_bfloat16 g_Bth2[(size_t)2048 * 1024];
__device__ __align__(256) __nv_bfloat16 g_Btl2[(size_t)2048 * 1024];
__device__ __align__(256) int g_deg [NN];
__device__ __align__(256) int g_cnt [NN];
__device__ __align__(256) int g_rowptr[NN + 1];
__device__ __align__(256) int g_csr [ET];
__device__ int g_is64;

// ---------------------------------------------------------------------------
// PTX helpers (baseline sm_80+ features: cp.async / ldmatrix / mma.sync)
// ---------------------------------------------------------------------------
__device__ __forceinline__ uint32_t smem_u32(const void* p) {
    uint32_t a;
    asm("{ .reg .u64 t; cvta.to.shared.u64 t, %1; cvt.u32.u64 %0, t; }" : "=r"(a) : "l"(p));
    return a;
}
__device__ __forceinline__ void cp16(uint32_t saddr, const void* g, int sz) {
    asm volatile("cp.async.ca.shared.global [%0], [%1], 16, %2;"
                 :: "r"(saddr), "l"(g), "r"(sz));
}
#define CP_COMMIT() asm volatile("cp.async.commit_group;" ::: "memory")
#define CP_WAIT1()  asm volatile("cp.async.wait_group 1;" ::: "memory")

#define LDSM4(r, addr) \
    asm volatile("ldmatrix.sync.aligned.m8n8.x4.shared.b16 {%0,%1,%2,%3}, [%4];" \
                 : "=r"((r)[0]), "=r"((r)[1]), "=r"((r)[2]), "=r"((r)[3]) : "r"(addr))

#define MMA16816(c, a, b) \
    asm volatile("mma.sync.aligned.m16n8k16.row.col.f32.bf16.bf16.f32 " \
                 "{%0,%1,%2,%3}, {%4,%5,%6,%7}, {%8,%9}, {%0,%1,%2,%3};" \
                 : "+f"((c)[0]), "+f"((c)[1]), "+f"((c)[2]), "+f"((c)[3]) \
                 : "r"((a)[0]), "r"((a)[1]), "r"((a)[2]), "r"((a)[3]), \
                   "r"((b)[0]), "r"((b)[1]))

// ---------------------------------------------------------------------------
// Edge dtype detection (int64 buffers: odd 32-bit words zero since idx<10000)
// ---------------------------------------------------------------------------
__global__ void detect_kernel(const unsigned int* w) {
    unsigned int acc = 0;
    for (int i = 1; i < 64; i += 2) acc |= w[i];
    g_is64 = (acc == 0) ? 1 : 0;
}

__device__ __forceinline__ void edge_nodes(const void* ei, int e, int& src, int& dst) {
    if (e >= EE) { src = dst = e - EE; return; }
    if (g_is64) {
        const long long* p = (const long long*)ei;
        src = (int)p[e]; dst = (int)p[EE + e];
    } else {
        const int* p = (const int*)ei;
        src = p[e]; dst = p[EE + e];
    }
}

// ---------------------------------------------------------------------------
// CSR build
// ---------------------------------------------------------------------------
__global__ void zero_csr_kernel(int* deg, int* cnt) {
    const int i = blockIdx.x * blockDim.x + threadIdx.x;
    if (i < NN) { deg[i] = 0; cnt[i] = 0; }
}
__global__ void count_kernel(const void* __restrict__ ei, int* deg) {
    const int e = blockIdx.x * blockDim.x + threadIdx.x;
    if (e >= ET) return;
    int src, dst;
    edge_nodes(ei, e, src, dst);
    atomicAdd(&deg[dst], 1);
}
// Warp-shuffle hierarchical scan, single block of 1024 threads.
__global__ void scan_kernel(const int* __restrict__ deg, int* rowptr) {
    __shared__ int wsum[32];
    __shared__ int carry_s;
    const int tid = threadIdx.x, lane = tid & 31, w = tid >> 5;
    if (tid == 0) carry_s = 0;
    __syncthreads();
    for (int base = 0; base < NN; base += 1024) {
        const int i = base + tid;
        const int v = (i < NN) ? deg[i] : 0;
        int x = v;
        #pragma unroll
        for (int o = 1; o < 32; o <<= 1) {
            const int t = __shfl_up_sync(0xffffffffu, x, o);
            if (lane >= o) x += t;
        }
        if (lane == 31) wsum[w] = x;
        __syncthreads();
        if (w == 0) {
            int s = wsum[lane];
            #pragma unroll
            for (int o = 1; o < 32; o <<= 1) {
                const int t = __shfl_up_sync(0xffffffffu, s, o);
                if (lane >= o) s += t;
            }
            wsum[lane] = s;
        }
        __syncthreads();
        const int excl = x - v + (w ? wsum[w - 1] : 0) + carry_s;
        if (i < NN) rowptr[i] = excl;
        __syncthreads();
        if (tid == 1023) carry_s = excl + v;
        __syncthreads();
    }
    if (tid == 0) rowptr[NN] = carry_s;
}
__global__ void scatter_kernel(const void* __restrict__ ei,
                               const int* __restrict__ rowptr, int* cnt, int* csr) {
    const int e = blockIdx.x * blockDim.x + threadIdx.x;
    if (e >= ET) return;
    int src, dst;
    edge_nodes(ei, e, src, dst);
    const int pos = rowptr[dst] + atomicAdd(&cnt[dst], 1);
    csr[pos] = src;
}

// ---------------------------------------------------------------------------
// fp32 -> bf16 hi/lo split (only for the primary input x0)
// ---------------------------------------------------------------------------
__global__ void convA_kernel(const float* __restrict__ x,
                             __nv_bfloat16* __restrict__ hi,
                             __nv_bfloat16* __restrict__ lo, int n4) {
    const int i = blockIdx.x * blockDim.x + threadIdx.x;
    if (i >= n4) return;
    const float4 v = ((const float4*)x)[i];
    __nv_bfloat16 h[4], l[4];
    const float vv[4] = {v.x, v.y, v.z, v.w};
    #pragma unroll
    for (int j = 0; j < 4; j++) {
        h[j] = __float2bfloat16(vv[j]);
        l[j] = __float2bfloat16(vv[j] - __bfloat162float(h[j]));
    }
    *(uint2*)(hi + (size_t)i * 4) = *(uint2*)h;
    *(uint2*)(lo + (size_t)i * 4) = *(uint2*)l;
}

// ---------------------------------------------------------------------------
// W [K][Nw] fp32 -> Bt [rowoff+Nw][ldout] bf16 hi/lo (transposed)
// ---------------------------------------------------------------------------
__global__ void convB_kernel(const float* __restrict__ W, int K, int Nw,
                             __nv_bfloat16* __restrict__ outh,
                             __nv_bfloat16* __restrict__ outl,
                             int rowoff, int ldout) {
    __shared__ float t[32][33];
    const int n0 = blockIdx.x * 32, k0 = blockIdx.y * 32;
    const int tx = threadIdx.x, ty = threadIdx.y;
    #pragma unroll
    for (int j = 0; j < 4; j++) {
        const int k = k0 + ty + j * 8, n = n0 + tx;
        if (k < K && n < Nw) t[ty + j * 8][tx] = W[(size_t)k * Nw + n];
    }
    __syncthreads();
    #pragma unroll
    for (int j = 0; j < 4; j++) {
        const int n = n0 + ty + j * 8, k = k0 + tx;
        if (n < Nw && k < K) {
            const float v = t[tx][ty + j * 8];
            const __nv_bfloat16 h = __float2bfloat16(v);
            outh[(size_t)(rowoff + n) * ldout + k] = h;
            outl[(size_t)(rowoff + n) * ldout + k] = __float2bfloat16(v - __bfloat162float(h));
        }
    }
}

__global__ void zero_bf16_kernel(__nv_bfloat16* a, __nv_bfloat16* b, int n) {
    const int i = blockIdx.x * blockDim.x + threadIdx.x;
    if (i < n) { a[i] = __float2bfloat16(0.f); b[i] = __float2bfloat16(0.f); }
}
__global__ void zero_f32_kernel(float* a, int na, float* b, int nb) {
    const int i = blockIdx.x * blockDim.x + threadIdx.x;
    if (i < na) a[i] = 0.f;
    if (i < nb) b[i] = 0.f;
}

// ---------------------------------------------------------------------------
// HMMA split-bf16 GEMM: C = Ah*Bh + Ah*Bl + Al*Bh (fp32 accuracy)
// 128x128 tile, 8 warps (64x32), K-stage 64 (two 32-K sub-chunks), double
// buffered cp.async -> barrier count halved vs 32-K stages (less tensor-pipe
// drain at 1 CTA/SM). Batched up-front B fragment loads (round-13 lesson).
// gridDim.z>1 -> split-K with red.global.add epilogue (outputs pre-zeroed).
// Column routing: n<split -> out0, else out1.
// ---------------------------------------------------------------------------
__global__ __launch_bounds__(256)
void hmma_gemm_kernel(const __nv_bfloat16* __restrict__ Ahg,
                      const __nv_bfloat16* __restrict__ Alg,
                      const __nv_bfloat16* __restrict__ Bhg,
                      const __nv_bfloat16* __restrict__ Blg,
                      int M, int K,
                      float* __restrict__ out0, int ld0, int split,
                      float* __restrict__ out1, int ld1, int nvalid) {
    extern __shared__ char smem[];
    constexpr int SUB = 32768;      // 16KB A + 16KB B per 32-K sub-chunk
    constexpr int STG = 2 * SUB;    // 64-K stage
    const int tid = threadIdx.x;
    const int lane = tid & 31, wid = tid >> 5;
    const int wm = wid >> 2, wn = wid & 3;
    const int m0 = blockIdx.y * 128, n0 = blockIdx.x * 128;
    const uint32_t sbase = smem_u32(smem);

    const int kpn = K / gridDim.z;
    const int kbase = blockIdx.z * kpn;
    const int nch = kpn >> 6;       // stages of 64

    float acc[4][4][4];
    #pragma unroll
    for (int i = 0; i < 4; i++)
        #pragma unroll
        for (int j = 0; j < 4; j++)
            #pragma unroll
            for (int k = 0; k < 4; k++) acc[i][j][k] = 0.f;

    const int g = lane >> 3, lr = lane & 7;
    const int xr = ((g & 1) << 3) + lr;
    const int cbase = g >> 1;
    const int swz = xr & 7;
    uint32_t aoff[4], boff[2];
    #pragma unroll
    for (int mt = 0; mt < 4; mt++) aoff[mt] = (uint32_t)((wm * 64 + mt * 16 + xr) * 128);
    #pragma unroll
    for (int np = 0; np < 2; np++) boff[np] = (uint32_t)((wn * 32 + np * 16 + xr) * 128);

    // loads one 32-K sub-chunk (old-style layout) at smem offset `soff`
    auto LOADSUB = [&](uint32_t soff, int k0) {
        const uint32_t sA = sbase + soff;
        const uint32_t sB = sA + 16384;
        #pragma unroll
        for (int i = 0; i < 4; i++) {
            const int ch = tid + i * 256;
            const int row = ch >> 3, c = ch & 7;
            const int m = m0 + row;
            const int mm = (m < M) ? m : 0;
            const __nv_bfloat16* srcA = (c < 4)
                ? Ahg + (size_t)mm * K + k0 + c * 8
                : Alg + (size_t)mm * K + k0 + (c - 4) * 8;
            cp16(sA + row * 128 + ((c ^ (row & 7)) << 4), srcA, (m < M) ? 16 : 0);
            const int n = n0 + row;
            const __nv_bfloat16* srcB = (c < 4)
                ? Bhg + (size_t)n * K + k0 + c * 8
                : Blg + (size_t)n * K + k0 + (c - 4) * 8;
            cp16(sB + row * 128 + ((c ^ (row & 7)) << 4), srcB, 16);
        }
    };
    auto LOADSTAGE = [&](int buf, int k0) {
        LOADSUB((uint32_t)buf * STG, k0);
        LOADSUB((uint32_t)buf * STG + SUB, k0 + 32);
    };

    LOADSTAGE(0, kbase);
    CP_COMMIT();

    for (int ci = 0; ci < nch; ci++) {
        if (ci + 1 < nch) LOADSTAGE((ci + 1) & 1, kbase + (ci + 1) * 64);
        CP_COMMIT();
        CP_WAIT1();
        __syncthreads();

        #pragma unroll
        for (int sub = 0; sub < 2; sub++) {
            const uint32_t sA = sbase + (uint32_t)(ci & 1) * STG + (uint32_t)sub * SUB;
            const uint32_t sB = sA + 16384;
            #pragma unroll
            for (int ks = 0; ks < 2; ks++) {
                const int ch = ks * 2 + cbase;
                uint32_t ah[4][4], al[4][4], bh[4][2], bl[4][2];
                #pragma unroll
                for (int mt = 0; mt < 4; mt++) {
                    LDSM4(ah[mt], sA + aoff[mt] + ((ch ^ swz) << 4));
                    LDSM4(al[mt], sA + aoff[mt] + (((ch + 4) ^ swz) << 4));
                }
                #pragma unroll
                for (int np = 0; np < 2; np++) {
                    uint32_t r[4];
                    LDSM4(r, sB + boff[np] + ((ch ^ swz) << 4));
                    bh[2 * np][0] = r[0]; bh[2 * np + 1][0] = r[1];
                    bh[2 * np][1] = r[2]; bh[2 * np + 1][1] = r[3];
                    LDSM4(r, sB + boff[np] + (((ch + 4) ^ swz) << 4));
                    bl[2 * np][0] = r[0]; bl[2 * np + 1][0] = r[1];
                    bl[2 * np][1] = r[2]; bl[2 * np + 1][1] = r[3];
                }
                #pragma unroll
                for (int mt = 0; mt < 4; mt++)
                    #pragma unroll
                    for (int nt = 0; nt < 4; nt++) {
                        MMA16816(acc[mt][nt], ah[mt], bh[nt]);
                        MMA16816(acc[mt][nt], ah[mt], bl[nt]);
                        MMA16816(acc[mt][nt], al[mt], bh[nt]);
                    }
            }
        }
        __syncthreads();
    }

    // epilogue
    const bool doadd = (gridDim.z > 1);
    const int mrow = lane >> 2, ncol = (lane & 3) << 1;
    #pragma unroll
    for (int mt = 0; mt < 4; mt++) {
        #pragma unroll
        for (int nt = 0; nt < 4; nt++) {
            const int n = n0 + wn * 32 + nt * 8 + ncol;
            if (n >= nvalid) continue;
            float* base;
            int nn;
            if (n < split) { base = out0; nn = n;         }
            else           { base = out1; nn = n - split; }
            const int ld = (n < split) ? ld0 : ld1;
            const int m1 = m0 + wm * 64 + mt * 16 + mrow;
            const int m2 = m1 + 8;
            if (doadd) {
                if (m1 < M)
                    asm volatile("red.global.add.v2.f32 [%0], {%1,%2};"
                                 :: "l"(base + (size_t)m1 * ld + nn),
                                    "f"(acc[mt][nt][0]), "f"(acc[mt][nt][1]) : "memory");
                if (m2 < M)
                    asm volatile("red.global.add.v2.f32 [%0], {%1,%2};"
                                 :: "l"(base + (size_t)m2 * ld + nn),
                                    "f"(acc[mt][nt][2]), "f"(acc[mt][nt][3]) : "memory");
            } else {
                if (m1 < M)
                    *(float2*)(base + (size_t)m1 * ld + nn) =
                        make_float2(acc[mt][nt][0], acc[mt][nt][1]);
                if (m2 < M)
                    *(float2*)(base + (size_t)m2 * ld + nn) =
                        make_float2(acc[mt][nt][2], acc[mt][nt][3]);
            }
        }
    }
}

// ---------------------------------------------------------------------------
// Attention coefficients, warp per (n,head), C=256, H=4
// ---------------------------------------------------------------------------
__global__ void attn_warp_kernel(const float* __restrict__ h,
                                 const float* __restrict__ a_s,
                                 const float* __restrict__ a_d,
                                 float* __restrict__ als, float* __restrict__ ald) {
    const int w = (blockIdx.x * blockDim.x + threadIdx.x) >> 5;
    if (w >= NN * 4) return;
    const int lane = threadIdx.x & 31;
    const int hh = w & 3;
    const float4* row = (const float4*)(h + (size_t)w * 256);
    const float4* as = (const float4*)(a_s + hh * 256);
    const float4* ad = (const float4*)(a_d + hh * 256);
    float s1 = 0.f, s2 = 0.f;
    #pragma unroll
    for (int i = 0; i < 2; i++) {
        const float4 v = row[lane + i * 32];
        const float4 a = as[lane + i * 32];
        const float4 b = ad[lane + i * 32];
        s1 += v.x * a.x + v.y * a.y + v.z * a.z + v.w * a.w;
        s2 += v.x * b.x + v.y * b.y + v.z * b.z + v.w * b.w;
    }
    #pragma unroll
    for (int o = 16; o; o >>= 1) {
        s1 += __shfl_xor_sync(0xffffffffu, s1, o);
        s2 += __shfl_xor_sync(0xffffffffu, s2, o);
    }
    if (lane == 0) { als[w] = s1; ald[w] = s2; }
}

// Layer 3 attention coefficients (H=6, C=6)
__global__ void attn_coeff3_kernel(const float* __restrict__ h,
                                   const float* __restrict__ a_s,
                                   const float* __restrict__ a_d,
                                   float* __restrict__ als, float* __restrict__ ald) {
    const int idx = blockIdx.x * blockDim.x + threadIdx.x;
    if (idx >= NN * 6) return;
    const int hh = idx % 6;
    const float* row = h + (size_t)idx * 6;
    const float* as = a_s + hh * 6;
    const float* ad = a_d + hh * 6;
    float s1 = 0.f, s2 = 0.f;
    #pragma unroll
    for (int c = 0; c < 6; c++) {
        const float v = row[c];
        s1 += v * as[c];
        s2 += v * ad[c];
    }
    als[idx] = s1;
    ald[idx] = s2;
}

// ---------------------------------------------------------------------------
// Fused CSR aggregation + epilogue for layers 1-2 (H=4, C=256):
// out = elu(sum_e alpha_e h[src_e] + b + lin + bl) -> bf16 hi/lo for next GEMM
// One block (256 thr) per dst; softmax without max-shift (logits O(1)).
// ---------------------------------------------------------------------------
__global__ __launch_bounds__(256)
void aggr_fused_kernel(const int* __restrict__ rowptr, const int* __restrict__ csr,
                       const float* __restrict__ h,
                       const float* __restrict__ als, const float* __restrict__ ald,
                       const float* __restrict__ b, const float* __restrict__ lin,
                       const float* __restrict__ bl,
                       __nv_bfloat16* __restrict__ oh, __nv_bfloat16* __restrict__ ol) {
    __shared__ float s_ex[DCAP * 4];
    __shared__ int   s_src[DCAP];
    __shared__ float s_sum[4];
    const int dst = blockIdx.x;
    const int rs = rowptr[dst], re = rowptr[dst + 1];
    const int deg = re - rs;
    const int tid = threadIdx.x;
    if (tid < 4) s_sum[tid] = 0.f;
    __syncthreads();

    // Phase A: exp(leaky(logit)) per (edge, head) + denominator
    for (int idx = tid; idx < deg * 4; idx += 256) {
        const int e = idx >> 2, hh = idx & 3;
        const int src = csr[rs + e];
        if (hh == 0 && e < DCAP) s_src[e] = src;
        float v = als[src * 4 + hh] + ald[dst * 4 + hh];
        v = v > 0.f ? v : NEG * v;
        const float ex = __expf(v);
        if (e < DCAP) s_ex[e * 4 + hh] = ex;
        atomicAdd(&s_sum[hh], ex);
    }
    __syncthreads();

    // Phase B: weighted gather; thread owns 4 channels (same head)
    const int head = tid >> 6;
    const float isum = 1.f / (s_sum[head] + 1e-16f);
    float4 acc = make_float4(0.f, 0.f, 0.f, 0.f);
    #pragma unroll 2
    for (int e = 0; e < deg; e++) {
        int src; float ex;
        if (e < DCAP) { src = s_src[e]; ex = s_ex[e * 4 + head]; }
        else {
            src = csr[rs + e];
            float v = als[src * 4 + head] + ald[dst * 4 + head];
            v = v > 0.f ? v : NEG * v;
            ex = __expf(v);
        }
        const float a = ex * isum;
        const float4 hv = *(const float4*)(h + (size_t)src * HID + tid * 4);
        acc.x += a * hv.x; acc.y += a * hv.y; acc.z += a * hv.z; acc.w += a * hv.w;
    }

    // Epilogue: + b + lin + bl, ELU, split to bf16 hi/lo
    const float4 lv  = *(const float4*)(lin + (size_t)dst * HID + tid * 4);
    const float4 b4  = *(const float4*)(b + tid * 4);
    const float4 bl4 = *(const float4*)(bl + tid * 4);
    float vals[4] = { acc.x + lv.x + b4.x + bl4.x, acc.y + lv.y + b4.y + bl4.y,
                      acc.z + lv.z + b4.z + bl4.z, acc.w + lv.w + b4.w + bl4.w };
    __nv_bfloat16 hi[4], lo[4];
    #pragma unroll
    for (int j = 0; j < 4; j++) {
        const float v = vals[j] > 0.f ? vals[j] : expm1f(vals[j]);
        hi[j] = __float2bfloat16(v);
        lo[j] = __float2bfloat16(v - __bfloat162float(hi[j]));
    }
    *(uint2*)(oh + (size_t)dst * HID + tid * 4) = *(uint2*)hi;
    *(uint2*)(ol + (size_t)dst * HID + tid * 4) = *(uint2*)lo;
}

// ---------------------------------------------------------------------------
// Fused layer-3 aggregation + head-mean + biases + residual + log_softmax.
// One block (64 thr) per dst.
// ---------------------------------------------------------------------------
__global__ __launch_bounds__(64)
void aggr3_fused_kernel(const int* __restrict__ rowptr, const int* __restrict__ csr,
                        const float* __restrict__ h3,
                        const float* __restrict__ als, const float* __restrict__ ald,
                        const float* __restrict__ b3, const float* __restrict__ lin3,
                        const float* __restrict__ bl3,
                        float* __restrict__ out) {
    __shared__ float s_ex[DCAP3 * 6];
    __shared__ int   s_src[DCAP3];
    __shared__ float s_sum[6];
    __shared__ float s_val[36];
    __shared__ float s_lg[6];
    const int dst = blockIdx.x;
    const int rs = rowptr[dst], re = rowptr[dst + 1];
    const int deg = re - rs;
    const int tid = threadIdx.x;
    if (tid < 6) s_sum[tid] = 0.f;
    __syncthreads();

    for (int idx = tid; idx < deg * 6; idx += 64) {
        const int e = idx / 6, hh = idx - e * 6;
        const int src = csr[rs + e];
        if (hh == 0 && e < DCAP3) s_src[e] = src;
        float v = als[src * 6 + hh] + ald[dst * 6 + hh];
        v = v > 0.f ? v : NEG * v;
        const float ex = __expf(v);
        if (e < DCAP3) s_ex[e * 6 + hh] = ex;
        atomicAdd(&s_sum[hh], ex);
    }
    __syncthreads();

    if (tid < 36) {
        const int c = tid;
        const int head = c / 6;
        const float isum = 1.f / (s_sum[head] + 1e-16f);
        float acc = 0.f;
        for (int e = 0; e < deg; e++) {
            int src; float ex;
            if (e < DCAP3) { src = s_src[e]; ex = s_ex[e * 6 + head]; }
            else {
                src = csr[rs + e];
                float v = als[src * 6 + head] + ald[dst * 6 + head];
                v = v > 0.f ? v : NEG * v;
                ex = __expf(v);
            }
            acc += ex * isum * h3[(size_t)src * 36 + c];
        }
        s_val[c] = acc;
    }
    __syncthreads();

    if (tid < 6) {
        const int c = tid;
        float m = 0.f;
        #pragma unroll
        for (int hh = 0; hh < 6; hh++) m += s_val[hh * 6 + c];
        s_lg[c] = m * (1.f / 6.f) + b3[c] + lin3[dst * 6 + c] + bl3[c];
    }
    __syncthreads();
    if (tid < 6) {
        float mx = s_lg[0];
        #pragma unroll
        for (int c = 1; c < 6; c++) mx = fmaxf(mx, s_lg[c]);
        float se = 0.f;
        #pragma unroll
        for (int c = 0; c < 6; c++) se += expf(s_lg[c] - mx);
        const float lse = logf(se) + mx;
        out[dst * 6 + tid] = s_lg[tid] - lse;
    }
}

// ---------------------------------------------------------------------------
// Host launcher — round-8/11 structure: fork/join side streams hide CSR build
// + weight conversion under the GEMMs; whole-M GEMMs. Streams/events created
// ONCE (first call = correctness run), reused.
// ---------------------------------------------------------------------------
extern "C" void kernel_launch(void* const* d_in, const int* in_sizes, int n_in,
                              void* d_out, int out_size) {
    const float* x0  = (const float*)d_in[0];
    const void*  ei  = d_in[1];
    const float* W1  = (const float*)d_in[2];
    const float* as1 = (const float*)d_in[3];
    const float* ad1 = (const float*)d_in[4];
    const float* b1  = (const float*)d_in[5];
    const float* Wl1 = (const float*)d_in[6];
    const float* bl1 = (const float*)d_in[7];
    const float* W2  = (const float*)d_in[8];
    const float* as2 = (const float*)d_in[9];
    const float* ad2 = (const float*)d_in[10];
    const float* b2  = (const float*)d_in[11];
    const float* Wl2 = (const float*)d_in[12];
    const float* bl2 = (const float*)d_in[13];
    const float* W3  = (const float*)d_in[14];
    const float* as3 = (const float*)d_in[15];
    const float* ad3 = (const float*)d_in[16];
    const float* b3  = (const float*)d_in[17];
    const float* Wl3 = (const float*)d_in[18];
    const float* bl3 = (const float*)d_in[19];
    float* out = (float*)d_out;

    float *h, *lin, *als, *ald, *h3, *lin3;
    __nv_bfloat16 *Axh, *Axl, *Bth, *Btl, *Bth2, *Btl2;
    int *deg, *cnt, *rowptr, *csr;
    cudaGetSymbolAddress((void**)&h,    g_h);
    cudaGetSymbolAddress((void**)&lin,  g_lin);
    cudaGetSymbolAddress((void**)&als,  g_als);
    cudaGetSymbolAddress((void**)&ald,  g_ald);
    cudaGetSymbolAddress((void**)&h3,   g_h3);
    cudaGetSymbolAddress((void**)&lin3, g_lin3);
    cudaGetSymbolAddress((void**)&Axh,  g_Axh);
    cudaGetSymbolAddress((void**)&Axl,  g_Axl);
    cudaGetSymbolAddress((void**)&Bth,  g_Bth);
    cudaGetSymbolAddress((void**)&Btl,  g_Btl);
    cudaGetSymbolAddress((void**)&Bth2, g_Bth2);
    cudaGetSymbolAddress((void**)&Btl2, g_Btl2);
    cudaGetSymbolAddress((void**)&deg,  g_deg);
    cudaGetSymbolAddress((void**)&cnt,  g_cnt);
    cudaGetSymbolAddress((void**)&rowptr, g_rowptr);
    cudaGetSymbolAddress((void**)&csr,  g_csr);

    const int SMEMB = 131072;   // 2 stages x 64KB
    cudaFuncSetAttribute(hmma_gemm_kernel,
                         cudaFuncAttributeMaxDynamicSharedMemorySize, SMEMB);

    const dim3 cbT(32, 8);
    const int egrid = (ET + 255) / 256;

    // One-time stream/event creation (reused every call).
    static cudaStream_t s1 = nullptr, s2 = nullptr;
    static cudaEvent_t evRoot, evCsr, evB1, evG1, evB2, evB3, evJ1, evJ2;
    if (s1 == nullptr) {
        cudaStreamCreateWithFlags(&s1, cudaStreamNonBlocking);
        cudaStreamCreateWithFlags(&s2, cudaStreamNonBlocking);
        cudaEventCreateWithFlags(&evRoot, cudaEventDisableTiming);
        cudaEventCreateWithFlags(&evCsr,  cudaEventDisableTiming);
        cudaEventCreateWithFlags(&evB1,   cudaEventDisableTiming);
        cudaEventCreateWithFlags(&evG1,   cudaEventDisableTiming);
        cudaEventCreateWithFlags(&evB2,   cudaEventDisableTiming);
        cudaEventCreateWithFlags(&evB3,   cudaEventDisableTiming);
        cudaEventCreateWithFlags(&evJ1,   cudaEventDisableTiming);
        cudaEventCreateWithFlags(&evJ2,   cudaEventDisableTiming);
    }

    // Fork
    cudaEventRecord(evRoot, 0);
    cudaStreamWaitEvent(s1, evRoot, 0);
    cudaStreamWaitEvent(s2, evRoot, 0);

    // ---- s1: CSR build (needed first by aggr1) ----
    detect_kernel<<<1, 1, 0, s1>>>((const unsigned int*)ei);
    zero_csr_kernel<<<(NN + 255) / 256, 256, 0, s1>>>(deg, cnt);
    count_kernel<<<egrid, 256, 0, s1>>>(ei, deg);
    scan_kernel<<<1, 1024, 0, s1>>>(deg, rowptr);
    scatter_kernel<<<egrid, 256, 0, s1>>>(ei, rowptr, cnt, csr);
    cudaEventRecord(evCsr, s1);

    // ---- s2: convB1 (needed by gemm1), then convB2 into buffer set 2 ----
    convB_kernel<<<dim3(32, 16), cbT, 0, s2>>>(W1,  512, 1024, Bth, Btl, 0,    512);
    convB_kernel<<<dim3(32, 16), cbT, 0, s2>>>(Wl1, 512, 1024, Bth, Btl, 1024, 512);
    cudaEventRecord(evB1, s2);
    convB_kernel<<<dim3(32, 32), cbT, 0, s2>>>(W2,  1024, 1024, Bth2, Btl2, 0,    1024);
    convB_kernel<<<dim3(32, 32), cbT, 0, s2>>>(Wl2, 1024, 1024, Bth2, Btl2, 1024, 1024);
    cudaEventRecord(evB2, s2);

    // ---- stream 0: main dependent chain ----
    convA_kernel<<<(NN * 512 / 4 + 255) / 256, 256>>>(x0, Axh, Axl, NN * 512 / 4);
    cudaStreamWaitEvent(0, evB1, 0);
    hmma_gemm_kernel<<<dim3(16, 79, 1), 256, SMEMB>>>(Axh, Axl, Bth, Btl,
        NN, 512, h, 1024, 1024, lin, 1024, 2048);
    cudaEventRecord(evG1, 0);
    attn_warp_kernel<<<5000, 256>>>(h, as1, ad1, als, ald);
    cudaStreamWaitEvent(0, evCsr, 0);
    aggr_fused_kernel<<<NN, 256>>>(rowptr, csr, h, als, ald, b1, lin, bl1, Axh, Axl);

    // ---- s2: after gemm1 released buffer set 1, prep layer-3 B + zeros ----
    cudaStreamWaitEvent(s2, evG1, 0);
    zero_bf16_kernel<<<(128 * 1024 + 255) / 256, 256, 0, s2>>>(Bth, Btl, 128 * 1024);
    convB_kernel<<<dim3(2, 32), cbT, 0, s2>>>(W3,  1024, 36, Bth, Btl, 0,  1024);
    convB_kernel<<<dim3(1, 32), cbT, 0, s2>>>(Wl3, 1024, 6,  Bth, Btl, 36, 1024);
    zero_f32_kernel<<<(NN * 36 + 255) / 256, 256, 0, s2>>>(h3, NN * 36, lin3, NN * 6);
    cudaEventRecord(evB3, s2);

    // ---- Layer 2 (K=1024, B from set 2) ----
    cudaStreamWaitEvent(0, evB2, 0);
    hmma_gemm_kernel<<<dim3(16, 79, 1), 256, SMEMB>>>(Axh, Axl, Bth2, Btl2,
        NN, 1024, h, 1024, 1024, lin, 1024, 2048);
    attn_warp_kernel<<<5000, 256>>>(h, as2, ad2, als, ald);
    aggr_fused_kernel<<<NN, 256>>>(rowptr, csr, h, als, ald, b2, lin, bl2, Axh, Axl);

    // ---- Layer 3 (K=1024, N tile=128 zero-padded, split-K=4) ----
    cudaStreamWaitEvent(0, evB3, 0);
    hmma_gemm_kernel<<<dim3(1, 79, 4), 256, SMEMB>>>(Axh, Axl, Bth, Btl,
        NN, 1024, h3, 36, 36, lin3, 6, 42);
    attn_coeff3_kernel<<<(NN * 6 + 255) / 256, 256>>>(h3, as3, ad3, als, ald);
    aggr3_fused_kernel<<<NN, 64>>>(rowptr, csr, h3, als, ald, b3, lin3, bl3, out);

    // Join side streams back into the capture stream (required for capture)
    cudaEventRecord(evJ1, s1);
    cudaStreamWaitEvent(0, evJ1, 0);
    cudaEventRecord(evJ2, s2);
    cudaStreamWaitEvent(0, evJ2, 0);
}

// round 16
// speedup vs baseline: 1.0289x; 1.0289x over previous
#include <cuda_runtime.h>
#include <cuda_bf16.h>
#include <math.h>
#include <stdint.h>

// Problem constants
#define NN   10000
#define EE   160000
#define ET   170000          // EE + NN self loops
#define DIN  512
#define HID  1024
#define NEG  0.2f
#define DCAP 512             // cached edges per dst (layers 1-2)
#define DCAP3 256            // cached edges per dst (layer 3)

// ---------------------------------------------------------------------------
// Scratch (device globals; no allocation allowed)
// ---------------------------------------------------------------------------
__device__ __align__(256) float g_h   [(size_t)NN * HID];
__device__ __align__(256) float g_lin [(size_t)NN * HID];
__device__ __align__(256) float g_als [NN * 6];
__device__ __align__(256) float g_ald [NN * 6];
__device__ __align__(256) float g_h3  [NN * 36];
__device__ __align__(256) float g_lin3[NN * 6];
__device__ __align__(256) __nv_bfloat16 g_Axh[(size_t)NN * HID];
__device__ __align__(256) __nv_bfloat16 g_Axl[(size_t)NN * HID];
__device__ __align__(256) __nv_bfloat16 g_Bth[(size_t)2048 * 1024];
__device__ __align__(256) __nv_bfloat16 g_Btl[(size_t)2048 * 1024];
__device__ __align__(256) __nv_bfloat16 g_Bth2[(size_t)2048 * 1024];
__device__ __align__(256) __nv_bfloat16 g_Btl2[(size_t)2048 * 1024];
__device__ __align__(256) int g_deg [NN];
__device__ __align__(256) int g_cnt [NN];
__device__ __align__(256) int g_rowptr[NN + 1];
__device__ __align__(256) int g_csr [ET];
__device__ int g_is64;

// ---------------------------------------------------------------------------
// PTX helpers (baseline sm_80+ features: cp.async / ldmatrix / mma.sync)
// ---------------------------------------------------------------------------
__device__ __forceinline__ uint32_t smem_u32(const void* p) {
    uint32_t a;
    asm("{ .reg .u64 t; cvta.to.shared.u64 t, %1; cvt.u32.u64 %0, t; }" : "=r"(a) : "l"(p));
    return a;
}
__device__ __forceinline__ void cp16(uint32_t saddr, const void* g, int sz) {
    asm volatile("cp.async.ca.shared.global [%0], [%1], 16, %2;"
                 :: "r"(saddr), "l"(g), "r"(sz));
}
#define CP_COMMIT() asm volatile("cp.async.commit_group;" ::: "memory")
#define CP_WAIT2()  asm volatile("cp.async.wait_group 2;" ::: "memory")

#define LDSM4(r, addr) \
    asm volatile("ldmatrix.sync.aligned.m8n8.x4.shared.b16 {%0,%1,%2,%3}, [%4];" \
                 : "=r"((r)[0]), "=r"((r)[1]), "=r"((r)[2]), "=r"((r)[3]) : "r"(addr))

#define MMA16816(c, a, b) \
    asm volatile("mma.sync.aligned.m16n8k16.row.col.f32.bf16.bf16.f32 " \
                 "{%0,%1,%2,%3}, {%4,%5,%6,%7}, {%8,%9}, {%0,%1,%2,%3};" \
                 : "+f"((c)[0]), "+f"((c)[1]), "+f"((c)[2]), "+f"((c)[3]) \
                 : "r"((a)[0]), "r"((a)[1]), "r"((a)[2]), "r"((a)[3]), \
                   "r"((b)[0]), "r"((b)[1]))

// ---------------------------------------------------------------------------
// Edge dtype detection (int64 buffers: odd 32-bit words zero since idx<10000)
// ---------------------------------------------------------------------------
__global__ void detect_kernel(const unsigned int* w) {
    unsigned int acc = 0;
    for (int i = 1; i < 64; i += 2) acc |= w[i];
    g_is64 = (acc == 0) ? 1 : 0;
}

__device__ __forceinline__ void edge_nodes(const void* ei, int e, int& src, int& dst) {
    if (e >= EE) { src = dst = e - EE; return; }
    if (g_is64) {
        const long long* p = (const long long*)ei;
        src = (int)p[e]; dst = (int)p[EE + e];
    } else {
        const int* p = (const int*)ei;
        src = p[e]; dst = p[EE + e];
    }
}

// ---------------------------------------------------------------------------
// CSR build
// ---------------------------------------------------------------------------
__global__ void zero_csr_kernel(int* deg, int* cnt) {
    const int i = blockIdx.x * blockDim.x + threadIdx.x;
    if (i < NN) { deg[i] = 0; cnt[i] = 0; }
}
__global__ void count_kernel(const void* __restrict__ ei, int* deg) {
    const int e = blockIdx.x * blockDim.x + threadIdx.x;
    if (e >= ET) return;
    int src, dst;
    edge_nodes(ei, e, src, dst);
    atomicAdd(&deg[dst], 1);
}
// Warp-shuffle hierarchical scan, single block of 1024 threads.
__global__ void scan_kernel(const int* __restrict__ deg, int* rowptr) {
    __shared__ int wsum[32];
    __shared__ int carry_s;
    const int tid = threadIdx.x, lane = tid & 31, w = tid >> 5;
    if (tid == 0) carry_s = 0;
    __syncthreads();
    for (int base = 0; base < NN; base += 1024) {
        const int i = base + tid;
        const int v = (i < NN) ? deg[i] : 0;
        int x = v;
        #pragma unroll
        for (int o = 1; o < 32; o <<= 1) {
            const int t = __shfl_up_sync(0xffffffffu, x, o);
            if (lane >= o) x += t;
        }
        if (lane == 31) wsum[w] = x;
        __syncthreads();
        if (w == 0) {
            int s = wsum[lane];
            #pragma unroll
            for (int o = 1; o < 32; o <<= 1) {
                const int t = __shfl_up_sync(0xffffffffu, s, o);
                if (lane >= o) s += t;
            }
            wsum[lane] = s;
        }
        __syncthreads();
        const int excl = x - v + (w ? wsum[w - 1] : 0) + carry_s;
        if (i < NN) rowptr[i] = excl;
        __syncthreads();
        if (tid == 1023) carry_s = excl + v;
        __syncthreads();
    }
    if (tid == 0) rowptr[NN] = carry_s;
}
__global__ void scatter_kernel(const void* __restrict__ ei,
                               const int* __restrict__ rowptr, int* cnt, int* csr) {
    const int e = blockIdx.x * blockDim.x + threadIdx.x;
    if (e >= ET) return;
    int src, dst;
    edge_nodes(ei, e, src, dst);
    const int pos = rowptr[dst] + atomicAdd(&cnt[dst], 1);
    csr[pos] = src;
}

// ---------------------------------------------------------------------------
// fp32 -> bf16 hi/lo split (only for the primary input x0)
// ---------------------------------------------------------------------------
__global__ void convA_kernel(const float* __restrict__ x,
                             __nv_bfloat16* __restrict__ hi,
                             __nv_bfloat16* __restrict__ lo, int n4) {
    const int i = blockIdx.x * blockDim.x + threadIdx.x;
    if (i >= n4) return;
    const float4 v = ((const float4*)x)[i];
    __nv_bfloat16 h[4], l[4];
    const float vv[4] = {v.x, v.y, v.z, v.w};
    #pragma unroll
    for (int j = 0; j < 4; j++) {
        h[j] = __float2bfloat16(vv[j]);
        l[j] = __float2bfloat16(vv[j] - __bfloat162float(h[j]));
    }
    *(uint2*)(hi + (size_t)i * 4) = *(uint2*)h;
    *(uint2*)(lo + (size_t)i * 4) = *(uint2*)l;
}

// ---------------------------------------------------------------------------
// W [K][Nw] fp32 -> Bt [rowoff+Nw][ldout] bf16 hi/lo (transposed)
// ---------------------------------------------------------------------------
__global__ void convB_kernel(const float* __restrict__ W, int K, int Nw,
                             __nv_bfloat16* __restrict__ outh,
                             __nv_bfloat16* __restrict__ outl,
                             int rowoff, int ldout) {
    __shared__ float t[32][33];
    const int n0 = blockIdx.x * 32, k0 = blockIdx.y * 32;
    const int tx = threadIdx.x, ty = threadIdx.y;
    #pragma unroll
    for (int j = 0; j < 4; j++) {
        const int k = k0 + ty + j * 8, n = n0 + tx;
        if (k < K && n < Nw) t[ty + j * 8][tx] = W[(size_t)k * Nw + n];
    }
    __syncthreads();
    #pragma unroll
    for (int j = 0; j < 4; j++) {
        const int n = n0 + ty + j * 8, k = k0 + tx;
        if (n < Nw && k < K) {
            const float v = t[tx][ty + j * 8];
            const __nv_bfloat16 h = __float2bfloat16(v);
            outh[(size_t)(rowoff + n) * ldout + k] = h;
            outl[(size_t)(rowoff + n) * ldout + k] = __float2bfloat16(v - __bfloat162float(h));
        }
    }
}

__global__ void zero_bf16_kernel(__nv_bfloat16* a, __nv_bfloat16* b, int n) {
    const int i = blockIdx.x * blockDim.x + threadIdx.x;
    if (i < n) { a[i] = __float2bfloat16(0.f); b[i] = __float2bfloat16(0.f); }
}
__global__ void zero_f32_kernel(float* a, int na, float* b, int nb) {
    const int i = blockIdx.x * blockDim.x + threadIdx.x;
    if (i < na) a[i] = 0.f;
    if (i < nb) b[i] = 0.f;
}

// ---------------------------------------------------------------------------
// HMMA split-bf16 GEMM: C = Ah*Bh + Ah*Bl + Al*Bh (fp32 accuracy)
// 128x128 tile, 8 warps (64x32), 3-stage cp.async pipeline, K-stage 32.
// Batched up-front B fragment loads (4-deep LDSM MLP before the MMA block).
// gridDim.z>1 -> split-K with red.global.add epilogue (outputs pre-zeroed).
// Column routing: n<split -> out0, else out1.
// ---------------------------------------------------------------------------
__global__ __launch_bounds__(256)
void hmma_gemm_kernel(const __nv_bfloat16* __restrict__ Ahg,
                      const __nv_bfloat16* __restrict__ Alg,
                      const __nv_bfloat16* __restrict__ Bhg,
                      const __nv_bfloat16* __restrict__ Blg,
                      int M, int K,
                      float* __restrict__ out0, int ld0, int split,
                      float* __restrict__ out1, int ld1, int nvalid) {
    extern __shared__ char smem[];
    constexpr int STG = 32768;      // 16KB A + 16KB B per stage
    const int tid = threadIdx.x;
    const int lane = tid & 31, wid = tid >> 5;
    const int wm = wid >> 2, wn = wid & 3;
    const int m0 = blockIdx.y * 128, n0 = blockIdx.x * 128;
    const uint32_t sbase = smem_u32(smem);

    const int kpn = K / gridDim.z;
    const int kbase = blockIdx.z * kpn;
    const int nch = kpn >> 5;

    float acc[4][4][4];
    #pragma unroll
    for (int i = 0; i < 4; i++)
        #pragma unroll
        for (int j = 0; j < 4; j++)
            #pragma unroll
            for (int k = 0; k < 4; k++) acc[i][j][k] = 0.f;

    const int g = lane >> 3, lr = lane & 7;
    const int xr = ((g & 1) << 3) + lr;
    const int cbase = g >> 1;
    const int swz = xr & 7;
    uint32_t aoff[4], boff[2];
    #pragma unroll
    for (int mt = 0; mt < 4; mt++) aoff[mt] = (uint32_t)((wm * 64 + mt * 16 + xr) * 128);
    #pragma unroll
    for (int np = 0; np < 2; np++) boff[np] = (uint32_t)((wn * 32 + np * 16 + xr) * 128);

    auto LOADSTAGE = [&](int buf, int k0) {
        const uint32_t sA = sbase + buf * STG;
        const uint32_t sB = sA + 16384;
        #pragma unroll
        for (int i = 0; i < 4; i++) {
            const int ch = tid + i * 256;
            const int row = ch >> 3, c = ch & 7;
            const int m = m0 + row;
            const int mm = (m < M) ? m : 0;
            const __nv_bfloat16* srcA = (c < 4)
                ? Ahg + (size_t)mm * K + k0 + c * 8
                : Alg + (size_t)mm * K + k0 + (c - 4) * 8;
            cp16(sA + row * 128 + ((c ^ (row & 7)) << 4), srcA, (m < M) ? 16 : 0);
            const int n = n0 + row;
            const __nv_bfloat16* srcB = (c < 4)
                ? Bhg + (size_t)n * K + k0 + c * 8
                : Blg + (size_t)n * K + k0 + (c - 4) * 8;
            cp16(sB + row * 128 + ((c ^ (row & 7)) << 4), srcB, 16);
        }
    };

    LOADSTAGE(0, kbase);
    CP_COMMIT();
    if (nch > 1) LOADSTAGE(1, kbase + 32);
    CP_COMMIT();

    for (int ci = 0; ci < nch; ci++) {
        if (ci + 2 < nch) LOADSTAGE((ci + 2) % 3, kbase + (ci + 2) * 32);
        CP_COMMIT();
        CP_WAIT2();
        __syncthreads();

        const uint32_t sA = sbase + (ci % 3) * STG;
        const uint32_t sB = sA + 16384;
        #pragma unroll
        for (int ks = 0; ks < 2; ks++) {
            const int ch = ks * 2 + cbase;
            uint32_t ah[4][4], al[4][4], bh[4][2], bl[4][2];
            #pragma unroll
            for (int mt = 0; mt < 4; mt++) {
                LDSM4(ah[mt], sA + aoff[mt] + ((ch ^ swz) << 4));
                LDSM4(al[mt], sA + aoff[mt] + (((ch + 4) ^ swz) << 4));
            }
            #pragma unroll
            for (int np = 0; np < 2; np++) {
                uint32_t r[4];
                LDSM4(r, sB + boff[np] + ((ch ^ swz) << 4));
                bh[2 * np][0] = r[0]; bh[2 * np + 1][0] = r[1];
                bh[2 * np][1] = r[2]; bh[2 * np + 1][1] = r[3];
                LDSM4(r, sB + boff[np] + (((ch + 4) ^ swz) << 4));
                bl[2 * np][0] = r[0]; bl[2 * np + 1][0] = r[1];
                bl[2 * np][1] = r[2]; bl[2 * np + 1][1] = r[3];
            }
            #pragma unroll
            for (int mt = 0; mt < 4; mt++)
                #pragma unroll
                for (int nt = 0; nt < 4; nt++) {
                    MMA16816(acc[mt][nt], ah[mt], bh[nt]);
                    MMA16816(acc[mt][nt], ah[mt], bl[nt]);
                    MMA16816(acc[mt][nt], al[mt], bh[nt]);
                }
        }
        __syncthreads();
    }

    // epilogue
    const bool doadd = (gridDim.z > 1);
    const int mrow = lane >> 2, ncol = (lane & 3) << 1;
    #pragma unroll
    for (int mt = 0; mt < 4; mt++) {
        #pragma unroll
        for (int nt = 0; nt < 4; nt++) {
            const int n = n0 + wn * 32 + nt * 8 + ncol;
            if (n >= nvalid) continue;
            float* base;
            int nn;
            if (n < split) { base = out0; nn = n;         }
            else           { base = out1; nn = n - split; }
            const int ld = (n < split) ? ld0 : ld1;
            const int m1 = m0 + wm * 64 + mt * 16 + mrow;
            const int m2 = m1 + 8;
            if (doadd) {
                if (m1 < M)
                    asm volatile("red.global.add.v2.f32 [%0], {%1,%2};"
                                 :: "l"(base + (size_t)m1 * ld + nn),
                                    "f"(acc[mt][nt][0]), "f"(acc[mt][nt][1]) : "memory");
                if (m2 < M)
                    asm volatile("red.global.add.v2.f32 [%0], {%1,%2};"
                                 :: "l"(base + (size_t)m2 * ld + nn),
                                    "f"(acc[mt][nt][2]), "f"(acc[mt][nt][3]) : "memory");
            } else {
                if (m1 < M)
                    *(float2*)(base + (size_t)m1 * ld + nn) =
                        make_float2(acc[mt][nt][0], acc[mt][nt][1]);
                if (m2 < M)
                    *(float2*)(base + (size_t)m2 * ld + nn) =
                        make_float2(acc[mt][nt][2], acc[mt][nt][3]);
            }
        }
    }
}

// ---------------------------------------------------------------------------
// Attention coefficients, warp per (n,head), C=256, H=4
// ---------------------------------------------------------------------------
__global__ void attn_warp_kernel(const float* __restrict__ h,
                                 const float* __restrict__ a_s,
                                 const float* __restrict__ a_d,
                                 float* __restrict__ als, float* __restrict__ ald) {
    const int w = (blockIdx.x * blockDim.x + threadIdx.x) >> 5;
    if (w >= NN * 4) return;
    const int lane = threadIdx.x & 31;
    const int hh = w & 3;
    const float4* row = (const float4*)(h + (size_t)w * 256);
    const float4* as = (const float4*)(a_s + hh * 256);
    const float4* ad = (const float4*)(a_d + hh * 256);
    float s1 = 0.f, s2 = 0.f;
    #pragma unroll
    for (int i = 0; i < 2; i++) {
        const float4 v = row[lane + i * 32];
        const float4 a = as[lane + i * 32];
        const float4 b = ad[lane + i * 32];
        s1 += v.x * a.x + v.y * a.y + v.z * a.z + v.w * a.w;
        s2 += v.x * b.x + v.y * b.y + v.z * b.z + v.w * b.w;
    }
    #pragma unroll
    for (int o = 16; o; o >>= 1) {
        s1 += __shfl_xor_sync(0xffffffffu, s1, o);
        s2 += __shfl_xor_sync(0xffffffffu, s2, o);
    }
    if (lane == 0) { als[w] = s1; ald[w] = s2; }
}

// Layer 3 attention coefficients (H=6, C=6)
__global__ void attn_coeff3_kernel(const float* __restrict__ h,
                                   const float* __restrict__ a_s,
                                   const float* __restrict__ a_d,
                                   float* __restrict__ als, float* __restrict__ ald) {
    const int idx = blockIdx.x * blockDim.x + threadIdx.x;
    if (idx >= NN * 6) return;
    const int hh = idx % 6;
    const float* row = h + (size_t)idx * 6;
    const float* as = a_s + hh * 6;
    const float* ad = a_d + hh * 6;
    float s1 = 0.f, s2 = 0.f;
    #pragma unroll
    for (int c = 0; c < 6; c++) {
        const float v = row[c];
        s1 += v * as[c];
        s2 += v * ad[c];
    }
    als[idx] = s1;
    ald[idx] = s2;
}

// ---------------------------------------------------------------------------
// Fused CSR aggregation + epilogue for layers 1-2 (H=4, C=256):
// out = elu(sum_e alpha_e h[src_e] + b + lin + bl) -> bf16 hi/lo for next GEMM
// One block (256 thr) per dst; softmax without max-shift (logits O(1)).
// ---------------------------------------------------------------------------
__global__ __launch_bounds__(256)
void aggr_fused_kernel(const int* __restrict__ rowptr, const int* __restrict__ csr,
                       const float* __restrict__ h,
                       const float* __restrict__ als, const float* __restrict__ ald,
                       const float* __restrict__ b, const float* __restrict__ lin,
                       const float* __restrict__ bl,
                       __nv_bfloat16* __restrict__ oh, __nv_bfloat16* __restrict__ ol) {
    __shared__ float s_ex[DCAP * 4];
    __shared__ int   s_src[DCAP];
    __shared__ float s_sum[4];
    const int dst = blockIdx.x;
    const int rs = rowptr[dst], re = rowptr[dst + 1];
    const int deg = re - rs;
    const int tid = threadIdx.x;
    if (tid < 4) s_sum[tid] = 0.f;
    __syncthreads();

    // Phase A: exp(leaky(logit)) per (edge, head) + denominator
    for (int idx = tid; idx < deg * 4; idx += 256) {
        const int e = idx >> 2, hh = idx & 3;
        const int src = csr[rs + e];
        if (hh == 0 && e < DCAP) s_src[e] = src;
        float v = als[src * 4 + hh] + ald[dst * 4 + hh];
        v = v > 0.f ? v : NEG * v;
        const float ex = __expf(v);
        if (e < DCAP) s_ex[e * 4 + hh] = ex;
        atomicAdd(&s_sum[hh], ex);
    }
    __syncthreads();

    // Phase B: weighted gather; thread owns 4 channels (same head)
    const int head = tid >> 6;
    const float isum = 1.f / (s_sum[head] + 1e-16f);
    float4 acc = make_float4(0.f, 0.f, 0.f, 0.f);
    #pragma unroll 2
    for (int e = 0; e < deg; e++) {
        int src; float ex;
        if (e < DCAP) { src = s_src[e]; ex = s_ex[e * 4 + head]; }
        else {
            src = csr[rs + e];
            float v = als[src * 4 + head] + ald[dst * 4 + head];
            v = v > 0.f ? v : NEG * v;
            ex = __expf(v);
        }
        const float a = ex * isum;
        const float4 hv = *(const float4*)(h + (size_t)src * HID + tid * 4);
        acc.x += a * hv.x; acc.y += a * hv.y; acc.z += a * hv.z; acc.w += a * hv.w;
    }

    // Epilogue: + b + lin + bl, ELU, split to bf16 hi/lo
    const float4 lv  = *(const float4*)(lin + (size_t)dst * HID + tid * 4);
    const float4 b4  = *(const float4*)(b + tid * 4);
    const float4 bl4 = *(const float4*)(bl + tid * 4);
    float vals[4] = { acc.x + lv.x + b4.x + bl4.x, acc.y + lv.y + b4.y + bl4.y,
                      acc.z + lv.z + b4.z + bl4.z, acc.w + lv.w + b4.w + bl4.w };
    __nv_bfloat16 hi[4], lo[4];
    #pragma unroll
    for (int j = 0; j < 4; j++) {
        const float v = vals[j] > 0.f ? vals[j] : expm1f(vals[j]);
        hi[j] = __float2bfloat16(v);
        lo[j] = __float2bfloat16(v - __bfloat162float(hi[j]));
    }
    *(uint2*)(oh + (size_t)dst * HID + tid * 4) = *(uint2*)hi;
    *(uint2*)(ol + (size_t)dst * HID + tid * 4) = *(uint2*)lo;
}

// ---------------------------------------------------------------------------
// Fused layer-3 aggregation + head-mean + biases + residual + log_softmax.
// One block (64 thr) per dst.
// ---------------------------------------------------------------------------
__global__ __launch_bounds__(64)
void aggr3_fused_kernel(const int* __restrict__ rowptr, const int* __restrict__ csr,
                        const float* __restrict__ h3,
                        const float* __restrict__ als, const float* __restrict__ ald,
                        const float* __restrict__ b3, const float* __restrict__ lin3,
                        const float* __restrict__ bl3,
                        float* __restrict__ out) {
    __shared__ float s_ex[DCAP3 * 6];
    __shared__ int   s_src[DCAP3];
    __shared__ float s_sum[6];
    __shared__ float s_val[36];
    __shared__ float s_lg[6];
    const int dst = blockIdx.x;
    const int rs = rowptr[dst], re = rowptr[dst + 1];
    const int deg = re - rs;
    const int tid = threadIdx.x;
    if (tid < 6) s_sum[tid] = 0.f;
    __syncthreads();

    for (int idx = tid; idx < deg * 6; idx += 64) {
        const int e = idx / 6, hh = idx - e * 6;
        const int src = csr[rs + e];
        if (hh == 0 && e < DCAP3) s_src[e] = src;
        float v = als[src * 6 + hh] + ald[dst * 6 + hh];
        v = v > 0.f ? v : NEG * v;
        const float ex = __expf(v);
        if (e < DCAP3) s_ex[e * 6 + hh] = ex;
        atomicAdd(&s_sum[hh], ex);
    }
    __syncthreads();

    if (tid < 36) {
        const int c = tid;
        const int head = c / 6;
        const float isum = 1.f / (s_sum[head] + 1e-16f);
        float acc = 0.f;
        for (int e = 0; e < deg; e++) {
            int src; float ex;
            if (e < DCAP3) { src = s_src[e]; ex = s_ex[e * 6 + head]; }
            else {
                src = csr[rs + e];
                float v = als[src * 6 + head] + ald[dst * 6 + head];
                v = v > 0.f ? v : NEG * v;
                ex = __expf(v);
            }
            acc += ex * isum * h3[(size_t)src * 36 + c];
        }
        s_val[c] = acc;
    }
    __syncthreads();

    if (tid < 6) {
        const int c = tid;
        float m = 0.f;
        #pragma unroll
        for (int hh = 0; hh < 6; hh++) m += s_val[hh * 6 + c];
        s_lg[c] = m * (1.f / 6.f) + b3[c] + lin3[dst * 6 + c] + bl3[c];
    }
    __syncthreads();
    if (tid < 6) {
        float mx = s_lg[0];
        #pragma unroll
        for (int c = 1; c < 6; c++) mx = fmaxf(mx, s_lg[c]);
        float se = 0.f;
        #pragma unroll
        for (int c = 0; c < 6; c++) se += expf(s_lg[c] - mx);
        const float lse = logf(se) + mx;
        out[dst * 6 + tid] = s_lg[tid] - lse;
    }
}

// ---------------------------------------------------------------------------
// Host launcher — committed best (rounds 8/11/14, 864 µs): fork/join side
// streams hide CSR build + weight conversion under the GEMMs; whole-M GEMMs.
// Streams/events created ONCE (first call = correctness run), reused.
// ---------------------------------------------------------------------------
extern "C" void kernel_launch(void* const* d_in, const int* in_sizes, int n_in,
                              void* d_out, int out_size) {
    const float* x0  = (const float*)d_in[0];
    const void*  ei  = d_in[1];
    const float* W1  = (const float*)d_in[2];
    const float* as1 = (const float*)d_in[3];
    const float* ad1 = (const float*)d_in[4];
    const float* b1  = (const float*)d_in[5];
    const float* Wl1 = (const float*)d_in[6];
    const float* bl1 = (const float*)d_in[7];
    const float* W2  = (const float*)d_in[8];
    const float* as2 = (const float*)d_in[9];
    const float* ad2 = (const float*)d_in[10];
    const float* b2  = (const float*)d_in[11];
    const float* Wl2 = (const float*)d_in[12];
    const float* bl2 = (const float*)d_in[13];
    const float* W3  = (const float*)d_in[14];
    const float* as3 = (const float*)d_in[15];
    const float* ad3 = (const float*)d_in[16];
    const float* b3  = (const float*)d_in[17];
    const float* Wl3 = (const float*)d_in[18];
    const float* bl3 = (const float*)d_in[19];
    float* out = (float*)d_out;

    float *h, *lin, *als, *ald, *h3, *lin3;
    __nv_bfloat16 *Axh, *Axl, *Bth, *Btl, *Bth2, *Btl2;
    int *deg, *cnt, *rowptr, *csr;
    cudaGetSymbolAddress((void**)&h,    g_h);
    cudaGetSymbolAddress((void**)&lin,  g_lin);
    cudaGetSymbolAddress((void**)&als,  g_als);
    cudaGetSymbolAddress((void**)&ald,  g_ald);
    cudaGetSymbolAddress((void**)&h3,   g_h3);
    cudaGetSymbolAddress((void**)&lin3, g_lin3);
    cudaGetSymbolAddress((void**)&Axh,  g_Axh);
    cudaGetSymbolAddress((void**)&Axl,  g_Axl);
    cudaGetSymbolAddress((void**)&Bth,  g_Bth);
    cudaGetSymbolAddress((void**)&Btl,  g_Btl);
    cudaGetSymbolAddress((void**)&Bth2, g_Bth2);
    cudaGetSymbolAddress((void**)&Btl2, g_Btl2);
    cudaGetSymbolAddress((void**)&deg,  g_deg);
    cudaGetSymbolAddress((void**)&cnt,  g_cnt);
    cudaGetSymbolAddress((void**)&rowptr, g_rowptr);
    cudaGetSymbolAddress((void**)&csr,  g_csr);

    const int SMEMB = 98304;   // 3 stages x 32KB
    cudaFuncSetAttribute(hmma_gemm_kernel,
                         cudaFuncAttributeMaxDynamicSharedMemorySize, SMEMB);

    const dim3 cbT(32, 8);
    const int egrid = (ET + 255) / 256;

    // One-time stream/event creation (reused every call).
    static cudaStream_t s1 = nullptr, s2 = nullptr;
    static cudaEvent_t evRoot, evCsr, evB1, evG1, evB2, evB3, evJ1, evJ2;
    if (s1 == nullptr) {
        cudaStreamCreateWithFlags(&s1, cudaStreamNonBlocking);
        cudaStreamCreateWithFlags(&s2, cudaStreamNonBlocking);
        cudaEventCreateWithFlags(&evRoot, cudaEventDisableTiming);
        cudaEventCreateWithFlags(&evCsr,  cudaEventDisableTiming);
        cudaEventCreateWithFlags(&evB1,   cudaEventDisableTiming);
        cudaEventCreateWithFlags(&evG1,   cudaEventDisableTiming);
        cudaEventCreateWithFlags(&evB2,   cudaEventDisableTiming);
        cudaEventCreateWithFlags(&evB3,   cudaEventDisableTiming);
        cudaEventCreateWithFlags(&evJ1,   cudaEventDisableTiming);
        cudaEventCreateWithFlags(&evJ2,   cudaEventDisableTiming);
    }

    // Fork
    cudaEventRecord(evRoot, 0);
    cudaStreamWaitEvent(s1, evRoot, 0);
    cudaStreamWaitEvent(s2, evRoot, 0);

    // ---- s1: CSR build (needed first by aggr1) ----
    detect_kernel<<<1, 1, 0, s1>>>((const unsigned int*)ei);
    zero_csr_kernel<<<(NN + 255) / 256, 256, 0, s1>>>(deg, cnt);
    count_kernel<<<egrid, 256, 0, s1>>>(ei, deg);
    scan_kernel<<<1, 1024, 0, s1>>>(deg, rowptr);
    scatter_kernel<<<egrid, 256, 0, s1>>>(ei, rowptr, cnt, csr);
    cudaEventRecord(evCsr, s1);

    // ---- s2: convB1 (needed by gemm1), then convB2 into buffer set 2 ----
    convB_kernel<<<dim3(32, 16), cbT, 0, s2>>>(W1,  512, 1024, Bth, Btl, 0,    512);
    convB_kernel<<<dim3(32, 16), cbT, 0, s2>>>(Wl1, 512, 1024, Bth, Btl, 1024, 512);
    cudaEventRecord(evB1, s2);
    convB_kernel<<<dim3(32, 32), cbT, 0, s2>>>(W2,  1024, 1024, Bth2, Btl2, 0,    1024);
    convB_kernel<<<dim3(32, 32), cbT, 0, s2>>>(Wl2, 1024, 1024, Bth2, Btl2, 1024, 1024);
    cudaEventRecord(evB2, s2);

    // ---- stream 0: main dependent chain ----
    convA_kernel<<<(NN * 512 / 4 + 255) / 256, 256>>>(x0, Axh, Axl, NN * 512 / 4);
    cudaStreamWaitEvent(0, evB1, 0);
    hmma_gemm_kernel<<<dim3(16, 79, 1), 256, SMEMB>>>(Axh, Axl, Bth, Btl,
        NN, 512, h, 1024, 1024, lin, 1024, 2048);
    cudaEventRecord(evG1, 0);
    attn_warp_kernel<<<5000, 256>>>(h, as1, ad1, als, ald);
    cudaStreamWaitEvent(0, evCsr, 0);
    aggr_fused_kernel<<<NN, 256>>>(rowptr, csr, h, als, ald, b1, lin, bl1, Axh, Axl);

    // ---- s2: after gemm1 released buffer set 1, prep layer-3 B + zeros ----
    cudaStreamWaitEvent(s2, evG1, 0);
    zero_bf16_kernel<<<(128 * 1024 + 255) / 256, 256, 0, s2>>>(Bth, Btl, 128 * 1024);
    convB_kernel<<<dim3(2, 32), cbT, 0, s2>>>(W3,  1024, 36, Bth, Btl, 0,  1024);
    convB_kernel<<<dim3(1, 32), cbT, 0, s2>>>(Wl3, 1024, 6,  Bth, Btl, 36, 1024);
    zero_f32_kernel<<<(NN * 36 + 255) / 256, 256, 0, s2>>>(h3, NN * 36, lin3, NN * 6);
    cudaEventRecord(evB3, s2);

    // ---- Layer 2 (K=1024, B from set 2) ----
    cudaStreamWaitEvent(0, evB2, 0);
    hmma_gemm_kernel<<<dim3(16, 79, 1), 256, SMEMB>>>(Axh, Axl, Bth2, Btl2,
        NN, 1024, h, 1024, 1024, lin, 1024, 2048);
    attn_warp_kernel<<<5000, 256>>>(h, as2, ad2, als, ald);
    aggr_fused_kernel<<<NN, 256>>>(rowptr, csr, h, als, ald, b2, lin, bl2, Axh, Axl);

    // ---- Layer 3 (K=1024, N tile=128 zero-padded, split-K=4) ----
    cudaStreamWaitEvent(0, evB3, 0);
    hmma_gemm_kernel<<<dim3(1, 79, 4), 256, SMEMB>>>(Axh, Axl, Bth, Btl,
        NN, 1024, h3, 36, 36, lin3, 6, 42);
    attn_coeff3_kernel<<<(NN * 6 + 255) / 256, 256>>>(h3, as3, ad3, als, ald);
    aggr3_fused_kernel<<<NN, 64>>>(rowptr, csr, h3, als, ald, b3, lin3, bl3, out);

    // Join side streams back into the capture stream (required for capture)
    cudaEventRecord(evJ1, s1);
    cudaStreamWaitEvent(0, evJ1, 0);
    cudaEventRecord(evJ2, s2);
    cudaStreamWaitEvent(0, evJ2, 0);
}